// round 4
// baseline (speedup 1.0000x reference)
#include <cuda_runtime.h>
#include <cstdio>

#define SQ 256
#define BQ 256
#define DQ 256
#define HQ 8
#define STR (BQ * 32)   // floats per timestep in d_pre

// scratch: pre-activations, padded by 4 steps for branch-free prefetch
__device__ float d_pre[(SQ + 4) * STR];

__device__ __forceinline__ float htanh(float x) {
    float r;
    asm("tanh.approx.f32 %0, %1;" : "=f"(r) : "f"(x));
    return r;
}

// ---------------------------------------------------------------------------
// Kernel 1: pre[t,b,o] = x[t,b,:] @ Wx[o,:] + bias[o] + theta[o]
// ---------------------------------------------------------------------------
__global__ __launch_bounds__(256) void qlstm_gemm(
    const float* __restrict__ x,
    const float* __restrict__ Wf, const float* __restrict__ bf,
    const float* __restrict__ Wi, const float* __restrict__ bi,
    const float* __restrict__ Wu, const float* __restrict__ bu,
    const float* __restrict__ Wo, const float* __restrict__ bo,
    const float* __restrict__ thf, const float* __restrict__ thi,
    const float* __restrict__ thu, const float* __restrict__ tho)
{
    __shared__ float sW[32][260];
    __shared__ float sBias[32];

    int tid = threadIdx.x;

    #pragma unroll 4
    for (int idx = tid; idx < 32 * 256; idx += 256) {
        int o = idx >> 8;
        int d = idx & 255;
        int g = o >> 3, kk = o & 7;
        const float* Wg = (g == 0) ? Wf : (g == 1) ? Wi : (g == 2) ? Wu : Wo;
        sW[o][d] = Wg[kk * 264 + d];
    }
    if (tid < 32) {
        int g = tid >> 3, kk = tid & 7;
        const float* bg = (g == 0) ? bf : (g == 1) ? bi : (g == 2) ? bu : bo;
        const float* tg = (g == 0) ? thf : (g == 1) ? thi : (g == 2) ? thu : tho;
        sBias[tid] = bg[kk] + tg[kk];
    }
    __syncthreads();

    int warp = tid >> 5, lane = tid & 31;
    int o1 = lane & 15, o2 = o1 + 16;
    int rb = blockIdx.x * 128 + warp * 16 + (lane >> 4) * 8;

    float acc0[8], acc1[8];
    #pragma unroll
    for (int r = 0; r < 8; r++) { acc0[r] = 0.f; acc1[r] = 0.f; }

    const float* xp = x + (size_t)rb * 256;

    #pragma unroll 4
    for (int d = 0; d < 256; d += 4) {
        float4 w1 = *reinterpret_cast<const float4*>(&sW[o1][d]);
        float4 w2 = *reinterpret_cast<const float4*>(&sW[o2][d]);
        #pragma unroll
        for (int r = 0; r < 8; r++) {
            float4 xv = *reinterpret_cast<const float4*>(xp + r * 256 + d);
            acc0[r] = fmaf(xv.x, w1.x, acc0[r]);
            acc0[r] = fmaf(xv.y, w1.y, acc0[r]);
            acc0[r] = fmaf(xv.z, w1.z, acc0[r]);
            acc0[r] = fmaf(xv.w, w1.w, acc0[r]);
            acc1[r] = fmaf(xv.x, w2.x, acc1[r]);
            acc1[r] = fmaf(xv.y, w2.y, acc1[r]);
            acc1[r] = fmaf(xv.z, w2.z, acc1[r]);
            acc1[r] = fmaf(xv.w, w2.w, acc1[r]);
        }
    }

    float bb1 = sBias[o1], bb2 = sBias[o2];
    #pragma unroll
    for (int r = 0; r < 8; r++) {
        d_pre[(size_t)(rb + r) * 32 + o1] = acc0[r] + bb1;
        d_pre[(size_t)(rb + r) * 32 + o2] = acc1[r] + bb2;
    }
}

// ---------------------------------------------------------------------------
// Kernel 2: sequential LSTM. ONE WARP PER BLOCK, grid=256 (>=148 to dodge the
// low-grid SM issue throttle). lane = g*8+k; all-SHFL exchange; branch-free.
// ---------------------------------------------------------------------------
__global__ __launch_bounds__(32) void qlstm_recur(
    const float* __restrict__ Wf, const float* __restrict__ Wi,
    const float* __restrict__ Wu, const float* __restrict__ Wo,
    const float* __restrict__ hx, const float* __restrict__ cx,
    float* __restrict__ out)
{
    int w = blockIdx.x;
    int lane = threadIdx.x & 31;
    int g = lane >> 3, k = lane & 7;

    const float* Wg = (g == 0) ? Wf : (g == 1) ? Wi : (g == 2) ? Wu : Wo;
    float wh0 = Wg[k * 264 + 256 + 0], wh1 = Wg[k * 264 + 256 + 1];
    float wh2 = Wg[k * 264 + 256 + 2], wh3 = Wg[k * 264 + 256 + 3];
    float wh4 = Wg[k * 264 + 256 + 4], wh5 = Wg[k * 264 + 256 + 5];
    float wh6 = Wg[k * 264 + 256 + 6], wh7 = Wg[k * 264 + 256 + 7];

    // arg scale for tanh-based activation: sigmoid(x)=0.5+0.5*tanh(0.5x), u: tanh(x)
    float Mc = (g == 2) ? 1.0f : 0.5f;

    float h = hx[w * 8 + k];
    float c = cx[w * 8 + k];

    // prefetch pipeline, distance 4 (branch-free: d_pre padded)
    const float* pb = d_pre + w * 32 + lane;
    float q0 = pb[0 * STR], q1 = pb[1 * STR], q2 = pb[2 * STR], q3 = pb[3 * STR];
    const float* pf = pb + 4 * STR;

    float* op = out + (size_t)w * HQ + k;
    const unsigned FULL = 0xffffffffu;

    bool m1p = (k >= 1), m2p = (k >= 2), m3p = (k >= 3), m4p = (k >= 4),
         m5p = (k >= 5), m6p = (k >= 6), m7p = (k >= 7);

#define QSTEP(PQ)                                                            \
    {                                                                        \
        float h0 = __shfl_sync(FULL, h, 0, 8);                               \
        float h1 = __shfl_sync(FULL, h, 1, 8);                               \
        float h2 = __shfl_sync(FULL, h, 2, 8);                               \
        float h3 = __shfl_sync(FULL, h, 3, 8);                               \
        float h4 = __shfl_sync(FULL, h, 4, 8);                               \
        float h5 = __shfl_sync(FULL, h, 5, 8);                               \
        float h6 = __shfl_sync(FULL, h, 6, 8);                               \
        float h7 = __shfl_sync(FULL, h, 7, 8);                               \
        float ang = ((fmaf(wh0, h0, (PQ)) + wh1 * h1)                        \
                   + (wh2 * h2 + wh3 * h3))                                  \
                  + ((wh4 * h4 + wh5 * h5)                                   \
                   + (wh6 * h6 + wh7 * h7));                                 \
        float cv = __cosf(ang);                                              \
        float c0 = __shfl_sync(FULL, cv, 0, 8);                              \
        float c1 = __shfl_sync(FULL, cv, 1, 8);                              \
        float c2 = __shfl_sync(FULL, cv, 2, 8);                              \
        float c3 = __shfl_sync(FULL, cv, 3, 8);                              \
        float c4 = __shfl_sync(FULL, cv, 4, 8);                              \
        float c5 = __shfl_sync(FULL, cv, 5, 8);                              \
        float c6 = __shfl_sync(FULL, cv, 6, 8);                              \
        float c7 = __shfl_sync(FULL, cv, 7, 8);                              \
        float t0 = c0 * Mc;                                                  \
        float m1 = m1p ? c1 : 1.f;                                           \
        float m2 = m2p ? c2 : 1.f;                                           \
        float m3 = m3p ? c3 : 1.f;                                           \
        float m4 = m4p ? c4 : 1.f;                                           \
        float m5 = m5p ? c5 : 1.f;                                           \
        float m6 = m6p ? c6 : 1.f;                                           \
        float m7 = m7p ? c7 : 1.f;                                           \
        float p = ((t0 * m1) * (m2 * m3)) * ((m4 * m5) * (m6 * m7));         \
        float T = htanh(p);                                                  \
        float Tf = __shfl_sync(FULL, T, k);                                  \
        float Ti = __shfl_sync(FULL, T, 8 + k);                              \
        float Tu = __shfl_sync(FULL, T, 16 + k);                             \
        float To = __shfl_sync(FULL, T, 24 + k);                             \
        float fv = fmaf(0.5f, Tf, 0.5f);                                     \
        float iv = fmaf(0.5f, Ti, 0.5f);                                     \
        float ov = fmaf(0.5f, To, 0.5f);                                     \
        c = fmaf(fv, c, iv * Tu);                                            \
        h = ov * htanh(c);                                                   \
        *op = h;                                                             \
        op += BQ * HQ;                                                       \
    }

    for (int t = 0; t < SQ; t += 2) {
        QSTEP(q0); q0 = q2; q2 = pf[0]; pf += STR;
        QSTEP(q1); q1 = q3; q3 = pf[0]; pf += STR;
    }
#undef QSTEP

    // hT, cT (4x redundant same-value stores, benign)
    out[(size_t)SQ * BQ * HQ + (size_t)w * HQ + k] = h;
    out[(size_t)SQ * BQ * HQ + (size_t)BQ * HQ + (size_t)w * HQ + k] = c;
}

// ---------------------------------------------------------------------------
// Diagnostic: measure SM clock (printed to stdout; removed next round)
// ---------------------------------------------------------------------------
__global__ void clkprobe()
{
    unsigned long long t0, t1, c0, c1;
    asm volatile("mov.u64 %0, %%globaltimer;" : "=l"(t0));
    c0 = clock64();
    unsigned long long tgt = t0 + 2000;   // 2 us (globaltimer in ns)
    do { asm volatile("mov.u64 %0, %%globaltimer;" : "=l"(t1)); } while (t1 < tgt);
    c1 = clock64();
    printf("CLKPROBE %llu cyc over %llu ns = %.3f GHz\n",
           (unsigned long long)(c1 - c0), (unsigned long long)(t1 - t0),
           (double)(c1 - c0) / (double)(t1 - t0));
}

extern "C" void kernel_launch(void* const* d_in, const int* in_sizes, int n_in,
                              void* d_out, int out_size)
{
    const float* x   = (const float*)d_in[0];
    const float* hx  = (const float*)d_in[1];
    const float* cx  = (const float*)d_in[2];
    const float* Wf  = (const float*)d_in[3];
    const float* bf  = (const float*)d_in[4];
    const float* Wi  = (const float*)d_in[5];
    const float* bi  = (const float*)d_in[6];
    const float* Wu  = (const float*)d_in[7];
    const float* bu  = (const float*)d_in[8];
    const float* Wo  = (const float*)d_in[9];
    const float* bo  = (const float*)d_in[10];
    const float* tf  = (const float*)d_in[11];
    const float* ti  = (const float*)d_in[12];
    const float* tu  = (const float*)d_in[13];
    const float* to_ = (const float*)d_in[14];

    qlstm_gemm<<<512, 256>>>(x, Wf, bf, Wi, bi, Wu, bu, Wo, bo, tf, ti, tu, to_);
    qlstm_recur<<<256, 32>>>(Wf, Wi, Wu, Wo, hx, cx, (float*)d_out);
    clkprobe<<<1, 1>>>();
}

// round 5
// speedup vs baseline: 1.1278x; 1.1278x over previous
#include <cuda_runtime.h>

#define SQ 256
#define BQ 256
#define DQ 256
#define HQ 8
#define STR (BQ * 32)   // floats per timestep in d_pre

typedef unsigned long long ull;

// scratch: pre-activations, padded by 4 steps for branch-free prefetch
__device__ float d_pre[(SQ + 4) * STR];

__device__ __forceinline__ float htanh(float x) {
    float r;
    asm("tanh.approx.f32 %0, %1;" : "=f"(r) : "f"(x));
    return r;
}

// packed dual-FMA: d = a*b + d elementwise on f32x2
__device__ __forceinline__ void ffma2(ull& d, ull a, ull b) {
    asm("fma.rn.f32x2 %0, %1, %2, %3;" : "=l"(d) : "l"(a), "l"(b), "l"(d));
}

__device__ __forceinline__ float hsum2(ull v) {
    unsigned lo, hi;
    asm("mov.b64 {%0, %1}, %2;" : "=r"(lo), "=r"(hi) : "l"(v));
    return __uint_as_float(lo) + __uint_as_float(hi);
}

// ---------------------------------------------------------------------------
// Kernel 1: pre[t,b,o] = x[t,b,:] @ Wx[o,:] + bias[o] + theta[o]
// o = g*8+k over 4 gates. M=65536 rows, N=32, K=256.
// FMA stream halved via fma.rn.f32x2 (x + W consumed as native f32x2 pairs).
// ---------------------------------------------------------------------------
__global__ __launch_bounds__(256) void qlstm_gemm(
    const float* __restrict__ x,
    const float* __restrict__ Wf, const float* __restrict__ bf,
    const float* __restrict__ Wi, const float* __restrict__ bi,
    const float* __restrict__ Wu, const float* __restrict__ bu,
    const float* __restrict__ Wo, const float* __restrict__ bo,
    const float* __restrict__ thf, const float* __restrict__ thi,
    const float* __restrict__ thu, const float* __restrict__ tho)
{
    __shared__ float sW[32][260];   // stride 260 floats = 65*16B: rows stay 16B-aligned
    __shared__ float sBias[32];

    int tid = threadIdx.x;

    #pragma unroll 4
    for (int idx = tid; idx < 32 * 256; idx += 256) {
        int o = idx >> 8;
        int d = idx & 255;
        int g = o >> 3, kk = o & 7;
        const float* Wg = (g == 0) ? Wf : (g == 1) ? Wi : (g == 2) ? Wu : Wo;
        sW[o][d] = Wg[kk * 264 + d];
    }
    if (tid < 32) {
        int g = tid >> 3, kk = tid & 7;
        const float* bg = (g == 0) ? bf : (g == 1) ? bi : (g == 2) ? bu : bo;
        const float* tg = (g == 0) ? thf : (g == 1) ? thi : (g == 2) ? thu : tho;
        sBias[tid] = bg[kk] + tg[kk];
    }
    __syncthreads();

    int warp = tid >> 5, lane = tid & 31;
    int o1 = lane & 15, o2 = o1 + 16;
    int rb = blockIdx.x * 128 + warp * 16 + (lane >> 4) * 8;

    ull a0[8], a1[8];
    #pragma unroll
    for (int r = 0; r < 8; r++) { a0[r] = 0ULL; a1[r] = 0ULL; }

    const float* xp = x + (size_t)rb * 256;

    #pragma unroll 4
    for (int d = 0; d < 256; d += 4) {
        ulonglong2 w1 = *reinterpret_cast<const ulonglong2*>(&sW[o1][d]);
        ulonglong2 w2 = *reinterpret_cast<const ulonglong2*>(&sW[o2][d]);
        #pragma unroll
        for (int r = 0; r < 8; r++) {
            ulonglong2 xv = *reinterpret_cast<const ulonglong2*>(xp + r * 256 + d);
            ffma2(a0[r], xv.x, w1.x);
            ffma2(a0[r], xv.y, w1.y);
            ffma2(a1[r], xv.x, w2.x);
            ffma2(a1[r], xv.y, w2.y);
        }
    }

    float bb1 = sBias[o1], bb2 = sBias[o2];
    #pragma unroll
    for (int r = 0; r < 8; r++) {
        d_pre[(size_t)(rb + r) * 32 + o1] = hsum2(a0[r]) + bb1;
        d_pre[(size_t)(rb + r) * 32 + o2] = hsum2(a1[r]) + bb2;
    }
}

// ---------------------------------------------------------------------------
// Kernel 2: sequential LSTM. One warp per block, grid=256 (>=148 avoids the
// low-grid SM issue throttle). lane = g*8+k; all-SHFL exchange; branch-free.
// ---------------------------------------------------------------------------
__global__ __launch_bounds__(32) void qlstm_recur(
    const float* __restrict__ Wf, const float* __restrict__ Wi,
    const float* __restrict__ Wu, const float* __restrict__ Wo,
    const float* __restrict__ hx, const float* __restrict__ cx,
    float* __restrict__ out)
{
    int w = blockIdx.x;
    int lane = threadIdx.x & 31;
    int g = lane >> 3, k = lane & 7;

    const float* Wg = (g == 0) ? Wf : (g == 1) ? Wi : (g == 2) ? Wu : Wo;
    float wh0 = Wg[k * 264 + 256 + 0], wh1 = Wg[k * 264 + 256 + 1];
    float wh2 = Wg[k * 264 + 256 + 2], wh3 = Wg[k * 264 + 256 + 3];
    float wh4 = Wg[k * 264 + 256 + 4], wh5 = Wg[k * 264 + 256 + 5];
    float wh6 = Wg[k * 264 + 256 + 6], wh7 = Wg[k * 264 + 256 + 7];

    // arg scale: sigmoid(x)=0.5+0.5*tanh(0.5x) (f,i,o); u-gate: tanh(x)
    float Mc = (g == 2) ? 1.0f : 0.5f;

    float h = hx[w * 8 + k];
    float c = cx[w * 8 + k];

    // prefetch pipeline, distance 4 (branch-free: d_pre padded)
    const float* pb = d_pre + w * 32 + lane;
    float q0 = pb[0 * STR], q1 = pb[1 * STR], q2 = pb[2 * STR], q3 = pb[3 * STR];
    const float* pf = pb + 4 * STR;

    float* op = out + (size_t)w * HQ + k;
    const unsigned FULL = 0xffffffffu;

    bool m1p = (k >= 1), m2p = (k >= 2), m3p = (k >= 3), m4p = (k >= 4),
         m5p = (k >= 5), m6p = (k >= 6), m7p = (k >= 7);

#define QSTEP(PQ)                                                            \
    {                                                                        \
        float h0 = __shfl_sync(FULL, h, 0, 8);                               \
        float h1 = __shfl_sync(FULL, h, 1, 8);                               \
        float h2 = __shfl_sync(FULL, h, 2, 8);                               \
        float h3 = __shfl_sync(FULL, h, 3, 8);                               \
        float h4 = __shfl_sync(FULL, h, 4, 8);                               \
        float h5 = __shfl_sync(FULL, h, 5, 8);                               \
        float h6 = __shfl_sync(FULL, h, 6, 8);                               \
        float h7 = __shfl_sync(FULL, h, 7, 8);                               \
        float ang = ((fmaf(wh0, h0, (PQ)) + wh1 * h1)                        \
                   + (wh2 * h2 + wh3 * h3))                                  \
                  + ((wh4 * h4 + wh5 * h5)                                   \
                   + (wh6 * h6 + wh7 * h7));                                 \
        float cv = __cosf(ang);                                              \
        float c0 = __shfl_sync(FULL, cv, 0, 8);                              \
        float c1 = __shfl_sync(FULL, cv, 1, 8);                              \
        float c2 = __shfl_sync(FULL, cv, 2, 8);                              \
        float c3 = __shfl_sync(FULL, cv, 3, 8);                              \
        float c4 = __shfl_sync(FULL, cv, 4, 8);                              \
        float c5 = __shfl_sync(FULL, cv, 5, 8);                              \
        float c6 = __shfl_sync(FULL, cv, 6, 8);                              \
        float c7 = __shfl_sync(FULL, cv, 7, 8);                              \
        float t0 = c0 * Mc;                                                  \
        float m1 = m1p ? c1 : 1.f;                                           \
        float m2 = m2p ? c2 : 1.f;                                           \
        float m3 = m3p ? c3 : 1.f;                                           \
        float m4 = m4p ? c4 : 1.f;                                           \
        float m5 = m5p ? c5 : 1.f;                                           \
        float m6 = m6p ? c6 : 1.f;                                           \
        float m7 = m7p ? c7 : 1.f;                                           \
        float p = ((t0 * m1) * (m2 * m3)) * ((m4 * m5) * (m6 * m7));         \
        float T = htanh(p);                                                  \
        float Tf = __shfl_sync(FULL, T, k);                                  \
        float Ti = __shfl_sync(FULL, T, 8 + k);                              \
        float Tu = __shfl_sync(FULL, T, 16 + k);                             \
        float To = __shfl_sync(FULL, T, 24 + k);                             \
        float fv = fmaf(0.5f, Tf, 0.5f);                                     \
        float iv = fmaf(0.5f, Ti, 0.5f);                                     \
        float ov = fmaf(0.5f, To, 0.5f);                                     \
        c = fmaf(fv, c, iv * Tu);                                            \
        h = ov * htanh(c);                                                   \
        *op = h;                                                             \
        op += BQ * HQ;                                                       \
    }

    for (int t = 0; t < SQ; t += 2) {
        QSTEP(q0); q0 = q2; q2 = pf[0]; pf += STR;
        QSTEP(q1); q1 = q3; q3 = pf[0]; pf += STR;
    }
#undef QSTEP

    // hT, cT (4x redundant same-value stores, benign)
    out[(size_t)SQ * BQ * HQ + (size_t)w * HQ + k] = h;
    out[(size_t)SQ * BQ * HQ + (size_t)BQ * HQ + (size_t)w * HQ + k] = c;
}

extern "C" void kernel_launch(void* const* d_in, const int* in_sizes, int n_in,
                              void* d_out, int out_size)
{
    const float* x   = (const float*)d_in[0];
    const float* hx  = (const float*)d_in[1];
    const float* cx  = (const float*)d_in[2];
    const float* Wf  = (const float*)d_in[3];
    const float* bf  = (const float*)d_in[4];
    const float* Wi  = (const float*)d_in[5];
    const float* bi  = (const float*)d_in[6];
    const float* Wu  = (const float*)d_in[7];
    const float* bu  = (const float*)d_in[8];
    const float* Wo  = (const float*)d_in[9];
    const float* bo  = (const float*)d_in[10];
    const float* tf  = (const float*)d_in[11];
    const float* ti  = (const float*)d_in[12];
    const float* tu  = (const float*)d_in[13];
    const float* to_ = (const float*)d_in[14];

    qlstm_gemm<<<512, 256>>>(x, Wf, bf, Wi, bi, Wu, bu, Wo, bo, tf, ti, tu, to_);
    qlstm_recur<<<256, 32>>>(Wf, Wi, Wu, Wo, hx, cx, (float*)d_out);
}